// round 3
// baseline (speedup 1.0000x reference)
#include <cuda_runtime.h>
#include <cuda_bf16.h>
#include <cstdint>
#include <cstddef>

// Problem shapes
#define BB 8
#define NN 4096
#define EE 2048
#define DD 256
#define SCALE_F (0.0625f)            // 1/sqrt(256)
#define NEG_BIG (-9000000000000000.0f)
#define LN_EPS_F (1e-5f)

// GEMM tiling
#define TM 64
#define TN 64
#define TK 16

// ---------------------------------------------------------------------------
// Scratch (device globals: no allocation allowed)
// ---------------------------------------------------------------------------
__device__ float g_edge_ln[(size_t)BB * EE * DD];   // 16 MiB
__device__ float g_node_k[(size_t)BB * NN * DD];    // 32 MiB
__device__ float g_edge_h[(size_t)BB * EE * DD];    // 16 MiB
__device__ float g_edge_k[(size_t)BB * EE * DD];    // 16 MiB
__device__ float g_scores[(size_t)BB * EE * NN];    // 256 MiB (reused stage1+2)

// ---------------------------------------------------------------------------
// Reduction helpers
// ---------------------------------------------------------------------------
__device__ __forceinline__ float warpMax(float v) {
#pragma unroll
    for (int o = 16; o > 0; o >>= 1)
        v = fmaxf(v, __shfl_xor_sync(0xffffffffu, v, o));
    return v;
}
__device__ __forceinline__ float warpSum(float v) {
#pragma unroll
    for (int o = 16; o > 0; o >>= 1)
        v += __shfl_xor_sync(0xffffffffu, v, o);
    return v;
}

// ---------------------------------------------------------------------------
// LayerNorm: one block (256 thr) per row of D=256
// ---------------------------------------------------------------------------
__global__ void ln_kernel(const float* __restrict__ x,
                          const float* __restrict__ gam,
                          const float* __restrict__ bet,
                          float* __restrict__ y) {
    size_t row = blockIdx.x;
    int t = threadIdx.x;
    int w = t >> 5, l = t & 31;
    __shared__ float sred[8];

    float v = x[row * DD + t];

    // mean
    float s = warpSum(v);
    if (l == 0) sred[w] = s;
    __syncthreads();
    if (t < 32) {
        float x2 = (l < 8) ? sred[l] : 0.f;
        x2 = warpSum(x2);
        if (l == 0) sred[0] = x2;
    }
    __syncthreads();
    float mu = sred[0] * (1.0f / DD);
    __syncthreads();

    // variance
    float d = v - mu;
    float q = warpSum(d * d);
    if (l == 0) sred[w] = q;
    __syncthreads();
    if (t < 32) {
        float x2 = (l < 8) ? sred[l] : 0.f;
        x2 = warpSum(x2);
        if (l == 0) sred[0] = x2;
    }
    __syncthreads();
    float var = sred[0] * (1.0f / DD);

    y[row * DD + t] = gam[t] * d * rsqrtf(var + LN_EPS_F) + bet[t];
}

// ---------------------------------------------------------------------------
// Row softmax over L=4096: one block (256 thr) per row, 16 elems/thread
// ---------------------------------------------------------------------------
__global__ void softmax_kernel(float* __restrict__ S, int L) {
    float* row = S + (size_t)blockIdx.x * L;
    int t = threadIdx.x;
    int w = t >> 5, l = t & 31;
    const int PER = 16;
    __shared__ float sred[8];

    float v[PER];
    float mx = -3.4e38f;
#pragma unroll
    for (int i = 0; i < PER; i++) {
        v[i] = row[t + i * 256];
        mx = fmaxf(mx, v[i]);
    }
    mx = warpMax(mx);
    if (l == 0) sred[w] = mx;
    __syncthreads();
    if (t < 32) {
        float x2 = (l < 8) ? sred[l] : -3.4e38f;
        x2 = warpMax(x2);
        if (l == 0) sred[0] = x2;
    }
    __syncthreads();
    mx = sred[0];
    __syncthreads();

    float s = 0.f;
#pragma unroll
    for (int i = 0; i < PER; i++) {
        v[i] = __expf(v[i] - mx);
        s += v[i];
    }
    s = warpSum(s);
    if (l == 0) sred[w] = s;
    __syncthreads();
    if (t < 32) {
        float x2 = (l < 8) ? sred[l] : 0.f;
        x2 = warpSum(x2);
        if (l == 0) sred[0] = x2;
    }
    __syncthreads();
    float inv = 1.0f / sred[0];
#pragma unroll
    for (int i = 0; i < PER; i++)
        row[t + i * 256] = v[i] * inv;
}

// ---------------------------------------------------------------------------
// GEMM NN:  C[m,n] = sum_k A[m,k]*B[k,n]  (+ Cadd[m,n])
// A: [M,K] rm, B: [K,N] rm. Batched via blockIdx.z with element strides.
// ---------------------------------------------------------------------------
__global__ void gemm_nn_kernel(const float* __restrict__ A, const float* __restrict__ B,
                               const float* __restrict__ Cadd, float* __restrict__ C,
                               int M, int N, int K,
                               size_t sA, size_t sB, size_t sC, size_t sCadd) {
    int bz = blockIdx.z;
    A += (size_t)bz * sA;
    B += (size_t)bz * sB;
    C += (size_t)bz * sC;
    const float* Cp = Cadd ? (Cadd + (size_t)bz * sCadd) : nullptr;

    __shared__ float As[TK][TM];
    __shared__ float Bs[TK][TN];

    int t = threadIdx.x;
    int tx = t & 15, ty = t >> 4;
    int row0 = blockIdx.y * TM, col0 = blockIdx.x * TN;

    float acc[4][4];
#pragma unroll
    for (int i = 0; i < 4; i++)
#pragma unroll
        for (int j = 0; j < 4; j++) acc[i][j] = 0.f;

    for (int k0 = 0; k0 < K; k0 += TK) {
#pragma unroll
        for (int i = 0; i < 4; i++) {
            int idx = t + i * 256;
            int m = idx >> 4, kk = idx & 15;
            As[kk][m] = A[(size_t)(row0 + m) * K + (k0 + kk)];
        }
#pragma unroll
        for (int i = 0; i < 4; i++) {
            int idx = t + i * 256;
            int kk = idx >> 6, n = idx & 63;
            Bs[kk][n] = B[(size_t)(k0 + kk) * N + (col0 + n)];
        }
        __syncthreads();
#pragma unroll
        for (int kk = 0; kk < TK; kk++) {
            float a[4], bb[4];
#pragma unroll
            for (int i = 0; i < 4; i++) a[i] = As[kk][ty * 4 + i];
#pragma unroll
            for (int j = 0; j < 4; j++) bb[j] = Bs[kk][tx * 4 + j];
#pragma unroll
            for (int i = 0; i < 4; i++)
#pragma unroll
                for (int j = 0; j < 4; j++) acc[i][j] = fmaf(a[i], bb[j], acc[i][j]);
        }
        __syncthreads();
    }
#pragma unroll
    for (int i = 0; i < 4; i++) {
        int m = row0 + ty * 4 + i;
#pragma unroll
        for (int j = 0; j < 4; j++) {
            int n = col0 + tx * 4 + j;
            size_t o = (size_t)m * N + n;
            float v = acc[i][j];
            if (Cp) v += Cp[o];
            C[o] = v;
        }
    }
}

// ---------------------------------------------------------------------------
// GEMM A*B^T with fused mask+scale epilogue:
//   C[m,n] = Ht[m,n] > 0 ? scale * sum_k A[m,k]*B[n,k] : NEG_BIG
// A: [M,K] rm, B: [N,K] rm, Ht/C: [M,N].
// ---------------------------------------------------------------------------
__global__ void gemm_abt_mask_kernel(const float* __restrict__ A, const float* __restrict__ B,
                                     const int* __restrict__ Ht, float* __restrict__ C,
                                     int M, int N, int K, float scale,
                                     size_t sA, size_t sB, size_t sHt, size_t sC) {
    int bz = blockIdx.z;
    A += (size_t)bz * sA;
    B += (size_t)bz * sB;
    Ht += (size_t)bz * sHt;
    C += (size_t)bz * sC;

    __shared__ float As[TK][TM];
    __shared__ float Bs[TK][TN];

    int t = threadIdx.x;
    int tx = t & 15, ty = t >> 4;
    int row0 = blockIdx.y * TM, col0 = blockIdx.x * TN;

    float acc[4][4];
#pragma unroll
    for (int i = 0; i < 4; i++)
#pragma unroll
        for (int j = 0; j < 4; j++) acc[i][j] = 0.f;

    for (int k0 = 0; k0 < K; k0 += TK) {
#pragma unroll
        for (int i = 0; i < 4; i++) {
            int idx = t + i * 256;
            int m = idx >> 4, kk = idx & 15;
            As[kk][m] = A[(size_t)(row0 + m) * K + (k0 + kk)];
        }
#pragma unroll
        for (int i = 0; i < 4; i++) {
            int idx = t + i * 256;
            int n = idx >> 4, kk = idx & 15;
            Bs[kk][n] = B[(size_t)(col0 + n) * K + (k0 + kk)];
        }
        __syncthreads();
#pragma unroll
        for (int kk = 0; kk < TK; kk++) {
            float a[4], bb[4];
#pragma unroll
            for (int i = 0; i < 4; i++) a[i] = As[kk][ty * 4 + i];
#pragma unroll
            for (int j = 0; j < 4; j++) bb[j] = Bs[kk][tx * 4 + j];
#pragma unroll
            for (int i = 0; i < 4; i++)
#pragma unroll
                for (int j = 0; j < 4; j++) acc[i][j] = fmaf(a[i], bb[j], acc[i][j]);
        }
        __syncthreads();
    }
#pragma unroll
    for (int i = 0; i < 4; i++) {
        int m = row0 + ty * 4 + i;
#pragma unroll
        for (int j = 0; j < 4; j++) {
            int n = col0 + tx * 4 + j;
            size_t o = (size_t)m * N + n;
            C[o] = (Ht[o] > 0) ? acc[i][j] * scale : NEG_BIG;
        }
    }
}

// ---------------------------------------------------------------------------
// GEMM A^T*B:  C[m,n] = sum_k A[k*lda + m] * B[k*N + n]
// A: [K,M] rm (lda), B: [K,N] rm.
// ---------------------------------------------------------------------------
__global__ void gemm_tn_kernel(const float* __restrict__ A, const float* __restrict__ B,
                               float* __restrict__ C,
                               int M, int N, int K, int lda,
                               size_t sA, size_t sB, size_t sC) {
    int bz = blockIdx.z;
    A += (size_t)bz * sA;
    B += (size_t)bz * sB;
    C += (size_t)bz * sC;

    __shared__ float As[TK][TM];
    __shared__ float Bs[TK][TN];

    int t = threadIdx.x;
    int tx = t & 15, ty = t >> 4;
    int row0 = blockIdx.y * TM, col0 = blockIdx.x * TN;

    float acc[4][4];
#pragma unroll
    for (int i = 0; i < 4; i++)
#pragma unroll
        for (int j = 0; j < 4; j++) acc[i][j] = 0.f;

    for (int k0 = 0; k0 < K; k0 += TK) {
#pragma unroll
        for (int i = 0; i < 4; i++) {
            int idx = t + i * 256;
            int kk = idx >> 6, m = idx & 63;
            As[kk][m] = A[(size_t)(k0 + kk) * lda + (row0 + m)];
        }
#pragma unroll
        for (int i = 0; i < 4; i++) {
            int idx = t + i * 256;
            int kk = idx >> 6, n = idx & 63;
            Bs[kk][n] = B[(size_t)(k0 + kk) * N + (col0 + n)];
        }
        __syncthreads();
#pragma unroll
        for (int kk = 0; kk < TK; kk++) {
            float a[4], bb[4];
#pragma unroll
            for (int i = 0; i < 4; i++) a[i] = As[kk][ty * 4 + i];
#pragma unroll
            for (int j = 0; j < 4; j++) bb[j] = Bs[kk][tx * 4 + j];
#pragma unroll
            for (int i = 0; i < 4; i++)
#pragma unroll
                for (int j = 0; j < 4; j++) acc[i][j] = fmaf(a[i], bb[j], acc[i][j]);
        }
        __syncthreads();
    }
#pragma unroll
    for (int i = 0; i < 4; i++) {
        int m = row0 + ty * 4 + i;
#pragma unroll
        for (int j = 0; j < 4; j++) {
            int n = col0 + tx * 4 + j;
            C[(size_t)m * N + n] = acc[i][j];
        }
    }
}

// ---------------------------------------------------------------------------
// Launch
// ---------------------------------------------------------------------------
extern "C" void kernel_launch(void* const* d_in, const int* in_sizes, int n_in,
                              void* d_out, int out_size) {
    const float* hidden   = (const float*)d_in[0];   // [B,N,D]
    const int*   ht       = (const int*)d_in[1];     // [B,E,N]
    const float* edge_emb = (const float*)d_in[2];   // [B,E,D]
    const float* wnk      = (const float*)d_in[3];   // [D,D]
    const float* wek      = (const float*)d_in[4];   // [D,D]
    const float* gam      = (const float*)d_in[5];   // [D]
    const float* bet      = (const float*)d_in[6];   // [D]
    float* out = (float*)d_out;                      // [B,N,D]

    float *eln, *nk, *eh, *ek, *sc;
    cudaGetSymbolAddress((void**)&eln, g_edge_ln);
    cudaGetSymbolAddress((void**)&nk, g_node_k);
    cudaGetSymbolAddress((void**)&eh, g_edge_h);
    cudaGetSymbolAddress((void**)&ek, g_edge_k);
    cudaGetSymbolAddress((void**)&sc, g_scores);

    const size_t sED = (size_t)EE * DD;
    const size_t sND = (size_t)NN * DD;
    const size_t sEN = (size_t)EE * NN;

    // 1. edge_emb -> layernorm
    ln_kernel<<<BB * EE, 256>>>(edge_emb, gam, bet, eln);

    // 2. node_k = hidden @ wnk  (flatten batch into M)
    gemm_nn_kernel<<<dim3(DD / TN, (BB * NN) / TM, 1), 256>>>(
        hidden, wnk, nullptr, nk, BB * NN, DD, DD, 0, 0, 0, 0);

    // 3. edge_scores[b,e,n] = mask(ht, scale * edge_ln[e,:].node_k[n,:])
    gemm_abt_mask_kernel<<<dim3(NN / TN, EE / TM, BB), 256>>>(
        eln, nk, ht, sc, EE, NN, DD, SCALE_F, sED, sND, sEN, sEN);

    // 4. softmax over n (rows of [E,N])
    softmax_kernel<<<BB * EE, 256>>>(sc, NN);

    // 5. edge_h = attn @ hidden + edge_ln
    gemm_nn_kernel<<<dim3(DD / TN, EE / TM, BB), 256>>>(
        sc, hidden, eln, eh, EE, DD, NN, sEN, sND, sED, sED);

    // 6. edge_k = edge_h @ wek (flatten batch)
    gemm_nn_kernel<<<dim3(DD / TN, (BB * EE) / TM, 1), 256>>>(
        eh, wek, nullptr, ek, BB * EE, DD, DD, 0, 0, 0, 0);

    // 7. node_scores stored transposed as [b,e,n] = mask(ht, scale * edge_k[e].node_k[n])
    gemm_abt_mask_kernel<<<dim3(NN / TN, EE / TM, BB), 256>>>(
        ek, nk, ht, sc, EE, NN, DD, SCALE_F, sED, sND, sEN, sEN);

    // 8. softmax over n (rows of [E,N]) == softmax over axis=1 of [B,N,E]
    softmax_kernel<<<BB * EE, 256>>>(sc, NN);

    // 9. node_hidden[n,d] = sum_e attn2[e,n] * edge_h[e,d]  (A^T B, K=E)
    gemm_tn_kernel<<<dim3(DD / TN, NN / TM, BB), 256>>>(
        sc, eh, out, NN, DD, EE, NN, sEN, sED, sND);
}

// round 9
// speedup vs baseline: 3.1685x; 3.1685x over previous
#include <cuda_runtime.h>
#include <cuda_bf16.h>
#include <cstdint>
#include <cstddef>

// Problem shapes
#define BB 8
#define NN 4096
#define EE 2048
#define DD 256
#define SCALE_F (0.0625f)            // 1/sqrt(256)
#define NEG_BIG (-9000000000000000.0f)
#define LN_EPS_F (1e-5f)

// GEMM tiling
#define BM 128
#define BN 128
#define BK 32
#define RM_LD 36     // row-major (K-contig) smem row stride: conflict-free frags
#define KM_LD 136    // k-major (N-contig) smem row stride: conflict-free frags

// ---------------------------------------------------------------------------
// Scratch (device globals: no allocation allowed)
// ---------------------------------------------------------------------------
__device__ float g_edge_ln[(size_t)BB * EE * DD];   // 16 MiB
__device__ float g_node_k[(size_t)BB * NN * DD];    // 32 MiB
__device__ float g_edge_h[(size_t)BB * EE * DD];    // 16 MiB
__device__ float g_edge_k[(size_t)BB * EE * DD];    // 16 MiB
__device__ float g_scores[(size_t)BB * EE * NN];    // 256 MiB (reused stage1+2)

// ---------------------------------------------------------------------------
// Helpers
// ---------------------------------------------------------------------------
__device__ __forceinline__ float warpMax(float v) {
#pragma unroll
    for (int o = 16; o > 0; o >>= 1)
        v = fmaxf(v, __shfl_xor_sync(0xffffffffu, v, o));
    return v;
}
__device__ __forceinline__ float warpSum(float v) {
#pragma unroll
    for (int o = 16; o > 0; o >>= 1)
        v += __shfl_xor_sync(0xffffffffu, v, o);
    return v;
}

__device__ __forceinline__ float f2tf(float x) {
    uint32_t u;
    asm("cvt.rna.tf32.f32 %0, %1;" : "=r"(u) : "f"(x));
    return __uint_as_float(u);
}

__device__ __forceinline__ void mma_tf32(float c[4],
                                         uint32_t a0, uint32_t a1, uint32_t a2, uint32_t a3,
                                         uint32_t b0, uint32_t b1) {
    asm volatile(
        "mma.sync.aligned.m16n8k8.row.col.f32.tf32.tf32.f32 "
        "{%0,%1,%2,%3}, {%4,%5,%6,%7}, {%8,%9}, {%0,%1,%2,%3};"
        : "+f"(c[0]), "+f"(c[1]), "+f"(c[2]), "+f"(c[3])
        : "r"(a0), "r"(a1), "r"(a2), "r"(a3), "r"(b0), "r"(b1));
}

// ---------------------------------------------------------------------------
// LayerNorm: one block (256 thr) per row of D=256
// ---------------------------------------------------------------------------
__global__ void ln_kernel(const float* __restrict__ x,
                          const float* __restrict__ gam,
                          const float* __restrict__ bet,
                          float* __restrict__ y) {
    size_t row = blockIdx.x;
    int t = threadIdx.x;
    int w = t >> 5, l = t & 31;
    __shared__ float sred[8];

    float v = x[row * DD + t];

    float s = warpSum(v);
    if (l == 0) sred[w] = s;
    __syncthreads();
    if (t < 32) {
        float x2 = (l < 8) ? sred[l] : 0.f;
        x2 = warpSum(x2);
        if (l == 0) sred[0] = x2;
    }
    __syncthreads();
    float mu = sred[0] * (1.0f / DD);
    __syncthreads();

    float d = v - mu;
    float q = warpSum(d * d);
    if (l == 0) sred[w] = q;
    __syncthreads();
    if (t < 32) {
        float x2 = (l < 8) ? sred[l] : 0.f;
        x2 = warpSum(x2);
        if (l == 0) sred[0] = x2;
    }
    __syncthreads();
    float var = sred[0] * (1.0f / DD);

    y[row * DD + t] = gam[t] * d * rsqrtf(var + LN_EPS_F) + bet[t];
}

// ---------------------------------------------------------------------------
// Row softmax over L=4096: one block (256 thr) per row (already at DRAM roofline)
// ---------------------------------------------------------------------------
__global__ void softmax_kernel(float* __restrict__ S, int L) {
    float* row = S + (size_t)blockIdx.x * L;
    int t = threadIdx.x;
    int w = t >> 5, l = t & 31;
    const int PER = 16;
    __shared__ float sred[8];

    float v[PER];
    float mx = -3.4e38f;
#pragma unroll
    for (int i = 0; i < PER; i++) {
        v[i] = row[t + i * 256];
        mx = fmaxf(mx, v[i]);
    }
    mx = warpMax(mx);
    if (l == 0) sred[w] = mx;
    __syncthreads();
    if (t < 32) {
        float x2 = (l < 8) ? sred[l] : -3.4e38f;
        x2 = warpMax(x2);
        if (l == 0) sred[0] = x2;
    }
    __syncthreads();
    mx = sred[0];
    __syncthreads();

    float s = 0.f;
#pragma unroll
    for (int i = 0; i < PER; i++) {
        v[i] = __expf(v[i] - mx);
        s += v[i];
    }
    s = warpSum(s);
    if (l == 0) sred[w] = s;
    __syncthreads();
    if (t < 32) {
        float x2 = (l < 8) ? sred[l] : 0.f;
        x2 = warpSum(x2);
        if (l == 0) sred[0] = x2;
    }
    __syncthreads();
    float inv = 1.0f / sred[0];
#pragma unroll
    for (int i = 0; i < PER; i++)
        row[t + i * 256] = v[i] * inv;
}

// ---------------------------------------------------------------------------
// Unified tf32 tensor-core GEMM.
//   MODE 0 (nn):  C = A[M,K] * B[K,N]            lda=K, ldb=N
//   MODE 1 (abt): C = A[M,K] * B[N,K]^T          lda=K, ldb=K
//   MODE 2 (tn):  C = A[K,M]^T * B[K,N]          lda passed, ldb=N
// ADD: += Cadd ; MASK: C = Ht>0 ? v*scale : NEG_BIG
// Block: 256 thr = 8 warps (4x2), block tile 128x128, warp tile 32x64.
// All dims assumed multiples of the tile (true for this problem).
// ---------------------------------------------------------------------------
template <int MODE, bool ADD, bool MASK>
__global__ __launch_bounds__(256, 1)
void mma_gemm(const float* __restrict__ A, const float* __restrict__ B,
              const float* __restrict__ Cadd, const int* __restrict__ Ht,
              float* __restrict__ C,
              int M, int N, int K, int lda, float scale,
              size_t sA, size_t sB, size_t sC, size_t sAux) {
    int bz = blockIdx.z;
    A += (size_t)bz * sA;
    B += (size_t)bz * sB;
    C += (size_t)bz * sC;
    if (ADD) Cadd += (size_t)bz * sAux;
    if (MASK) Ht += (size_t)bz * sAux;

    constexpr int ASZ = (MODE == 2) ? BK * KM_LD : BM * RM_LD;
    constexpr int BSZ = (MODE == 1) ? BN * RM_LD : BK * KM_LD;
    __shared__ float As[ASZ];
    __shared__ float Bs[BSZ];

    const int t = threadIdx.x;
    const int lane = t & 31, wid = t >> 5;
    const int wm = wid >> 1, wn = wid & 1;
    const int grp = lane >> 2, thr = lane & 3;
    const int row0 = blockIdx.y * BM, col0 = blockIdx.x * BN;
    const int ldb = (MODE == 1) ? K : N;

    float acc[2][8][4];
#pragma unroll
    for (int i = 0; i < 2; i++)
#pragma unroll
        for (int j = 0; j < 8; j++)
#pragma unroll
            for (int q = 0; q < 4; q++) acc[i][j][q] = 0.f;

    for (int k0 = 0; k0 < K; k0 += BK) {
        // ---- load A tile ----
        if (MODE != 2) {
            // A is [M,K] row-major (K-contig): rows of 32 floats -> As[m][k]
#pragma unroll
            for (int i = 0; i < 4; i++) {
                int r = (t >> 3) + i * 32;
                int k4 = (t & 7) * 4;
                float4 v = *(const float4*)&A[(size_t)(row0 + r) * lda + k0 + k4];
                float4 w = make_float4(f2tf(v.x), f2tf(v.y), f2tf(v.z), f2tf(v.w));
                *(float4*)&As[r * RM_LD + k4] = w;
            }
        } else {
            // A is [K,M] (M-contig): k rows of 128 floats -> As[k][m]
#pragma unroll
            for (int i = 0; i < 4; i++) {
                int kk = (t >> 5) + i * 8;
                int c4 = (t & 31) * 4;
                float4 v = *(const float4*)&A[(size_t)(k0 + kk) * lda + row0 + c4];
                float4 w = make_float4(f2tf(v.x), f2tf(v.y), f2tf(v.z), f2tf(v.w));
                *(float4*)&As[kk * KM_LD + c4] = w;
            }
        }
        // ---- load B tile ----
        if (MODE != 1) {
            // B is [K,N] (N-contig): k rows of 128 floats -> Bs[k][n]
#pragma unroll
            for (int i = 0; i < 4; i++) {
                int kk = (t >> 5) + i * 8;
                int c4 = (t & 31) * 4;
                float4 v = *(const float4*)&B[(size_t)(k0 + kk) * ldb + col0 + c4];
                float4 w = make_float4(f2tf(v.x), f2tf(v.y), f2tf(v.z), f2tf(v.w));
                *(float4*)&Bs[kk * KM_LD + c4] = w;
            }
        } else {
            // B is [N,K] row-major (K-contig): rows of 32 floats -> Bs[n][k]
#pragma unroll
            for (int i = 0; i < 4; i++) {
                int r = (t >> 3) + i * 32;
                int k4 = (t & 7) * 4;
                float4 v = *(const float4*)&B[(size_t)(col0 + r) * ldb + k0 + k4];
                float4 w = make_float4(f2tf(v.x), f2tf(v.y), f2tf(v.z), f2tf(v.w));
                *(float4*)&Bs[r * RM_LD + k4] = w;
            }
        }
        __syncthreads();

        // ---- compute: 4 k8 steps ----
#pragma unroll
        for (int kk = 0; kk < BK; kk += 8) {
            uint32_t af[2][4];
#pragma unroll
            for (int i = 0; i < 2; i++) {
                int m0 = wm * 32 + i * 16;
                if (MODE != 2) {
                    af[i][0] = __float_as_uint(As[(m0 + grp) * RM_LD + kk + thr]);
                    af[i][1] = __float_as_uint(As[(m0 + grp + 8) * RM_LD + kk + thr]);
                    af[i][2] = __float_as_uint(As[(m0 + grp) * RM_LD + kk + thr + 4]);
                    af[i][3] = __float_as_uint(As[(m0 + grp + 8) * RM_LD + kk + thr + 4]);
                } else {
                    af[i][0] = __float_as_uint(As[(kk + thr) * KM_LD + m0 + grp]);
                    af[i][1] = __float_as_uint(As[(kk + thr) * KM_LD + m0 + grp + 8]);
                    af[i][2] = __float_as_uint(As[(kk + thr + 4) * KM_LD + m0 + grp]);
                    af[i][3] = __float_as_uint(As[(kk + thr + 4) * KM_LD + m0 + grp + 8]);
                }
            }
#pragma unroll
            for (int j = 0; j < 8; j++) {
                int n0 = wn * 64 + j * 8;
                uint32_t b0, b1;
                if (MODE != 1) {
                    b0 = __float_as_uint(Bs[(kk + thr) * KM_LD + n0 + grp]);
                    b1 = __float_as_uint(Bs[(kk + thr + 4) * KM_LD + n0 + grp]);
                } else {
                    b0 = __float_as_uint(Bs[(n0 + grp) * RM_LD + kk + thr]);
                    b1 = __float_as_uint(Bs[(n0 + grp) * RM_LD + kk + thr + 4]);
                }
#pragma unroll
                for (int i = 0; i < 2; i++)
                    mma_tf32(acc[i][j], af[i][0], af[i][1], af[i][2], af[i][3], b0, b1);
            }
        }
        __syncthreads();
    }

    // ---- epilogue ----
#pragma unroll
    for (int i = 0; i < 2; i++) {
        int rA = row0 + wm * 32 + i * 16 + grp;
        int rB = rA + 8;
#pragma unroll
        for (int j = 0; j < 8; j++) {
            int cn = col0 + wn * 64 + j * 8 + thr * 2;
            size_t oA = (size_t)rA * N + cn;
            size_t oB = (size_t)rB * N + cn;
            float v0 = acc[i][j][0], v1 = acc[i][j][1];
            float v2 = acc[i][j][2], v3 = acc[i][j][3];
            if (ADD) {
                v0 += Cadd[oA]; v1 += Cadd[oA + 1];
                v2 += Cadd[oB]; v3 += Cadd[oB + 1];
            }
            if (MASK) {
                v0 = (Ht[oA] > 0)     ? v0 * scale : NEG_BIG;
                v1 = (Ht[oA + 1] > 0) ? v1 * scale : NEG_BIG;
                v2 = (Ht[oB] > 0)     ? v2 * scale : NEG_BIG;
                v3 = (Ht[oB + 1] > 0) ? v3 * scale : NEG_BIG;
            }
            C[oA] = v0; C[oA + 1] = v1;
            C[oB] = v2; C[oB + 1] = v3;
        }
    }
}

// ---------------------------------------------------------------------------
// Launch
// ---------------------------------------------------------------------------
extern "C" void kernel_launch(void* const* d_in, const int* in_sizes, int n_in,
                              void* d_out, int out_size) {
    const float* hidden   = (const float*)d_in[0];   // [B,N,D]
    const int*   ht       = (const int*)d_in[1];     // [B,E,N]
    const float* edge_emb = (const float*)d_in[2];   // [B,E,D]
    const float* wnk      = (const float*)d_in[3];   // [D,D]
    const float* wek      = (const float*)d_in[4];   // [D,D]
    const float* gam      = (const float*)d_in[5];   // [D]
    const float* bet      = (const float*)d_in[6];   // [D]
    float* out = (float*)d_out;                      // [B,N,D]

    float *eln, *nk, *eh, *ek, *sc;
    cudaGetSymbolAddress((void**)&eln, g_edge_ln);
    cudaGetSymbolAddress((void**)&nk, g_node_k);
    cudaGetSymbolAddress((void**)&eh, g_edge_h);
    cudaGetSymbolAddress((void**)&ek, g_edge_k);
    cudaGetSymbolAddress((void**)&sc, g_scores);

    const size_t sED = (size_t)EE * DD;
    const size_t sND = (size_t)NN * DD;
    const size_t sEN = (size_t)EE * NN;

    // 1. edge_ln = layernorm(edge_emb)
    ln_kernel<<<BB * EE, 256>>>(edge_emb, gam, bet, eln);

    // 2. node_k = hidden @ wnk   (flatten batch: M=B*N, N=D, K=D)
    mma_gemm<0, false, false><<<dim3(DD / BN, (BB * NN) / BM, 1), 256>>>(
        hidden, wnk, nullptr, nullptr, nk,
        BB * NN, DD, DD, DD, 1.f, 0, 0, 0, 0);

    // 3. scores[b,e,n] = mask(ht, scale * edge_ln . node_k^T)   (M=E, N=N, K=D)
    mma_gemm<1, false, true><<<dim3(NN / BN, EE / BM, BB), 256>>>(
        eln, nk, nullptr, ht, sc,
        EE, NN, DD, DD, SCALE_F, sED, sND, sEN, sEN);

    // 4. softmax over n
    softmax_kernel<<<BB * EE, 256>>>(sc, NN);

    // 5. edge_h = attn @ hidden + edge_ln   (M=E, N=D, K=N)
    mma_gemm<0, true, false><<<dim3(DD / BN, EE / BM, BB), 256>>>(
        sc, hidden, eln, nullptr, eh,
        EE, DD, NN, NN, 1.f, sEN, sND, sED, sED);

    // 6. edge_k = edge_h @ wek   (flatten batch: M=B*E, N=D, K=D)
    mma_gemm<0, false, false><<<dim3(DD / BN, (BB * EE) / BM, 1), 256>>>(
        eh, wek, nullptr, nullptr, ek,
        BB * EE, DD, DD, DD, 1.f, 0, 0, 0, 0);

    // 7. scores[b,e,n] = mask(ht, scale * edge_k . node_k^T)
    mma_gemm<1, false, true><<<dim3(NN / BN, EE / BM, BB), 256>>>(
        ek, nk, nullptr, ht, sc,
        EE, NN, DD, DD, SCALE_F, sED, sND, sEN, sEN);

    // 8. softmax over n (== softmax over axis=1 of [B,N,E])
    softmax_kernel<<<BB * EE, 256>>>(sc, NN);

    // 9. out[n,d] = sum_e attn2[e,n] * edge_h[e,d]   (A^T B: M=N, N=D, K=E, lda=NN)
    mma_gemm<2, false, false><<<dim3(DD / BN, NN / BM, BB), 256>>>(
        sc, eh, nullptr, nullptr, out,
        NN, DD, EE, NN, 1.f, sEN, sED, sND, 0);
}

// round 10
// speedup vs baseline: 4.3575x; 1.3753x over previous
#include <cuda_runtime.h>
#include <cuda_bf16.h>
#include <cstdint>
#include <cstddef>

// Problem shapes
#define BB 8
#define NN 4096
#define EE 2048
#define DD 256
#define SCALE_F (0.0625f)            // 1/sqrt(256)
#define NEG_BIG (-9000000000000000.0f)
#define LN_EPS_F (1e-5f)

// GEMM tiling
#define BM 128
#define BN 128
#define BK 32
#define RM_LD 36     // row-major (K-contig) smem row stride (144B: 16B aligned, conflict-free)
#define KM_LD 136    // k-major (N-contig) smem row stride (544B: 16B aligned, conflict-free)

// ---------------------------------------------------------------------------
// Scratch (device globals: no allocation allowed)
// ---------------------------------------------------------------------------
__device__ float g_edge_ln[(size_t)BB * EE * DD];   // 16 MiB
__device__ float g_node_k[(size_t)BB * NN * DD];    // 32 MiB
__device__ float g_edge_h[(size_t)BB * EE * DD];    // 16 MiB
__device__ float g_edge_k[(size_t)BB * EE * DD];    // 16 MiB
__device__ float g_scores[(size_t)BB * EE * NN];    // 256 MiB (reused stage1+2)

// ---------------------------------------------------------------------------
// Helpers
// ---------------------------------------------------------------------------
__device__ __forceinline__ float warpMax(float v) {
#pragma unroll
    for (int o = 16; o > 0; o >>= 1)
        v = fmaxf(v, __shfl_xor_sync(0xffffffffu, v, o));
    return v;
}
__device__ __forceinline__ float warpSum(float v) {
#pragma unroll
    for (int o = 16; o > 0; o >>= 1)
        v += __shfl_xor_sync(0xffffffffu, v, o);
    return v;
}

// fp32 -> tf32 bits with round-to-nearest (applied in fragment path)
__device__ __forceinline__ uint32_t tf_bits(float x) {
    uint32_t u;
    asm("cvt.rna.tf32.f32 %0, %1;" : "=r"(u) : "f"(x));
    return u;
}

__device__ __forceinline__ void mma_tf32(float c[4],
                                         uint32_t a0, uint32_t a1, uint32_t a2, uint32_t a3,
                                         uint32_t b0, uint32_t b1) {
    asm volatile(
        "mma.sync.aligned.m16n8k8.row.col.f32.tf32.tf32.f32 "
        "{%0,%1,%2,%3}, {%4,%5,%6,%7}, {%8,%9}, {%0,%1,%2,%3};"
        : "+f"(c[0]), "+f"(c[1]), "+f"(c[2]), "+f"(c[3])
        : "r"(a0), "r"(a1), "r"(a2), "r"(a3), "r"(b0), "r"(b1));
}

// 16B global->shared async copy
__device__ __forceinline__ void cpa16(float* dst_smem, const float* src_gmem) {
    uint32_t d = (uint32_t)__cvta_generic_to_shared(dst_smem);
    asm volatile("cp.async.cg.shared.global [%0], [%1], 16;\n" :: "r"(d), "l"(src_gmem));
}
#define CP_COMMIT() asm volatile("cp.async.commit_group;\n" ::: "memory")
#define CP_WAIT1()  asm volatile("cp.async.wait_group 1;\n" ::: "memory")
#define CP_WAIT0()  asm volatile("cp.async.wait_group 0;\n" ::: "memory")

// ---------------------------------------------------------------------------
// LayerNorm: one block (256 thr) per row of D=256
// ---------------------------------------------------------------------------
__global__ void ln_kernel(const float* __restrict__ x,
                          const float* __restrict__ gam,
                          const float* __restrict__ bet,
                          float* __restrict__ y) {
    size_t row = blockIdx.x;
    int t = threadIdx.x;
    int w = t >> 5, l = t & 31;
    __shared__ float sred[8];

    float v = x[row * DD + t];

    float s = warpSum(v);
    if (l == 0) sred[w] = s;
    __syncthreads();
    if (t < 32) {
        float x2 = (l < 8) ? sred[l] : 0.f;
        x2 = warpSum(x2);
        if (l == 0) sred[0] = x2;
    }
    __syncthreads();
    float mu = sred[0] * (1.0f / DD);
    __syncthreads();

    float d = v - mu;
    float q = warpSum(d * d);
    if (l == 0) sred[w] = q;
    __syncthreads();
    if (t < 32) {
        float x2 = (l < 8) ? sred[l] : 0.f;
        x2 = warpSum(x2);
        if (l == 0) sred[0] = x2;
    }
    __syncthreads();
    float var = sred[0] * (1.0f / DD);

    y[row * DD + t] = gam[t] * d * rsqrtf(var + LN_EPS_F) + bet[t];
}

// ---------------------------------------------------------------------------
// Row softmax over L=4096: one block (256 thr) per row (already at DRAM roofline)
// ---------------------------------------------------------------------------
__global__ void softmax_kernel(float* __restrict__ S, int L) {
    float* row = S + (size_t)blockIdx.x * L;
    int t = threadIdx.x;
    int w = t >> 5, l = t & 31;
    const int PER = 16;
    __shared__ float sred[8];

    float v[PER];
    float mx = -3.4e38f;
#pragma unroll
    for (int i = 0; i < PER; i++) {
        v[i] = row[t + i * 256];
        mx = fmaxf(mx, v[i]);
    }
    mx = warpMax(mx);
    if (l == 0) sred[w] = mx;
    __syncthreads();
    if (t < 32) {
        float x2 = (l < 8) ? sred[l] : -3.4e38f;
        x2 = warpMax(x2);
        if (l == 0) sred[0] = x2;
    }
    __syncthreads();
    mx = sred[0];
    __syncthreads();

    float s = 0.f;
#pragma unroll
    for (int i = 0; i < PER; i++) {
        v[i] = __expf(v[i] - mx);
        s += v[i];
    }
    s = warpSum(s);
    if (l == 0) sred[w] = s;
    __syncthreads();
    if (t < 32) {
        float x2 = (l < 8) ? sred[l] : 0.f;
        x2 = warpSum(x2);
        if (l == 0) sred[0] = x2;
    }
    __syncthreads();
    float inv = 1.0f / sred[0];
#pragma unroll
    for (int i = 0; i < PER; i++)
        row[t + i * 256] = v[i] * inv;
}

// ---------------------------------------------------------------------------
// Unified tf32 tensor-core GEMM, 2-stage cp.async pipeline, 2 CTAs/SM.
//   MODE 0 (nn):  C = A[M,K] * B[K,N]            lda=K, ldb=N
//   MODE 1 (abt): C = A[M,K] * B[N,K]^T          lda=K, ldb=K
//   MODE 2 (tn):  C = A[K,M]^T * B[K,N]          lda passed, ldb=N
// ADD: += Cadd ; MASK: C = Ht>0 ? v*scale : NEG_BIG
// Block: 256 thr = 8 warps (4x2), block tile 128x128, warp tile 32x64.
// All dims are multiples of the tile for this problem.
// ---------------------------------------------------------------------------
template <int MODE, bool ADD, bool MASK>
__global__ __launch_bounds__(256, 2)
void mma_gemm(const float* __restrict__ A, const float* __restrict__ B,
              const float* __restrict__ Cadd, const int* __restrict__ Ht,
              float* __restrict__ C,
              int M, int N, int K, int lda, float scale,
              size_t sA, size_t sB, size_t sC, size_t sAux) {
    int bz = blockIdx.z;
    A += (size_t)bz * sA;
    B += (size_t)bz * sB;
    C += (size_t)bz * sC;
    if (ADD) Cadd += (size_t)bz * sAux;
    if (MASK) Ht += (size_t)bz * sAux;

    constexpr int ASZ = (MODE == 2) ? BK * KM_LD : BM * RM_LD;
    constexpr int BSZ = (MODE == 1) ? BN * RM_LD : BK * KM_LD;
    constexpr int STAGE = ASZ + BSZ;
    extern __shared__ float smem[];

    const int t = threadIdx.x;
    const int lane = t & 31, wid = t >> 5;
    const int wm = wid >> 1, wn = wid & 1;
    const int grp = lane >> 2, thr = lane & 3;
    const int row0 = blockIdx.y * BM, col0 = blockIdx.x * BN;
    const int ldb = (MODE == 1) ? K : N;

    // ---- async tile loader into stage s ----
    auto load_tile = [&](int s, int k0) {
        float* As = smem + s * STAGE;
        float* Bs = As + ASZ;
        if (MODE != 2) {
            // A [M,K] K-contig -> As[m][k]
#pragma unroll
            for (int i = 0; i < 4; i++) {
                int r = (t >> 3) + i * 32;
                int k4 = (t & 7) * 4;
                cpa16(&As[r * RM_LD + k4], &A[(size_t)(row0 + r) * lda + k0 + k4]);
            }
        } else {
            // A [K,M] M-contig -> As[k][m]
#pragma unroll
            for (int i = 0; i < 4; i++) {
                int kk = (t >> 5) + i * 8;
                int c4 = (t & 31) * 4;
                cpa16(&As[kk * KM_LD + c4], &A[(size_t)(k0 + kk) * lda + row0 + c4]);
            }
        }
        if (MODE != 1) {
            // B [K,N] N-contig -> Bs[k][n]
#pragma unroll
            for (int i = 0; i < 4; i++) {
                int kk = (t >> 5) + i * 8;
                int c4 = (t & 31) * 4;
                cpa16(&Bs[kk * KM_LD + c4], &B[(size_t)(k0 + kk) * ldb + col0 + c4]);
            }
        } else {
            // B [N,K] K-contig -> Bs[n][k]
#pragma unroll
            for (int i = 0; i < 4; i++) {
                int r = (t >> 3) + i * 32;
                int k4 = (t & 7) * 4;
                cpa16(&Bs[r * RM_LD + k4], &B[(size_t)(col0 + r) * ldb + k0 + k4]);
            }
        }
    };

    float acc[2][8][4];
#pragma unroll
    for (int i = 0; i < 2; i++)
#pragma unroll
        for (int j = 0; j < 8; j++)
#pragma unroll
            for (int q = 0; q < 4; q++) acc[i][j][q] = 0.f;

    const int ntiles = K / BK;

    // prologue: stage 0 in flight
    load_tile(0, 0);
    CP_COMMIT();

    for (int kt = 0; kt < ntiles; kt++) {
        const float* As = smem + (kt & 1) * STAGE;
        const float* Bs = As + ASZ;

        if (kt + 1 < ntiles) {
            load_tile((kt + 1) & 1, (kt + 1) * BK);
            CP_COMMIT();
            CP_WAIT1();           // tile kt has landed
        } else {
            CP_WAIT0();
        }
        __syncthreads();

        // ---- compute: 4 k8 steps on tile kt ----
#pragma unroll
        for (int kk = 0; kk < BK; kk += 8) {
            uint32_t af[2][4];
#pragma unroll
            for (int i = 0; i < 2; i++) {
                int m0 = wm * 32 + i * 16;
                if (MODE != 2) {
                    af[i][0] = tf_bits(As[(m0 + grp) * RM_LD + kk + thr]);
                    af[i][1] = tf_bits(As[(m0 + grp + 8) * RM_LD + kk + thr]);
                    af[i][2] = tf_bits(As[(m0 + grp) * RM_LD + kk + thr + 4]);
                    af[i][3] = tf_bits(As[(m0 + grp + 8) * RM_LD + kk + thr + 4]);
                } else {
                    af[i][0] = tf_bits(As[(kk + thr) * KM_LD + m0 + grp]);
                    af[i][1] = tf_bits(As[(kk + thr) * KM_LD + m0 + grp + 8]);
                    af[i][2] = tf_bits(As[(kk + thr + 4) * KM_LD + m0 + grp]);
                    af[i][3] = tf_bits(As[(kk + thr + 4) * KM_LD + m0 + grp + 8]);
                }
            }
#pragma unroll
            for (int j = 0; j < 8; j++) {
                int n0 = wn * 64 + j * 8;
                uint32_t b0, b1;
                if (MODE != 1) {
                    b0 = tf_bits(Bs[(kk + thr) * KM_LD + n0 + grp]);
                    b1 = tf_bits(Bs[(kk + thr + 4) * KM_LD + n0 + grp]);
                } else {
                    b0 = tf_bits(Bs[(n0 + grp) * RM_LD + kk + thr]);
                    b1 = tf_bits(Bs[(n0 + grp) * RM_LD + kk + thr + 4]);
                }
#pragma unroll
                for (int i = 0; i < 2; i++)
                    mma_tf32(acc[i][j], af[i][0], af[i][1], af[i][2], af[i][3], b0, b1);
            }
        }
        __syncthreads();   // tile kt fully consumed before its buffer is refilled
    }

    // ---- epilogue ----
#pragma unroll
    for (int i = 0; i < 2; i++) {
        int rA = row0 + wm * 32 + i * 16 + grp;
        int rB = rA + 8;
#pragma unroll
        for (int j = 0; j < 8; j++) {
            int cn = col0 + wn * 64 + j * 8 + thr * 2;
            size_t oA = (size_t)rA * N + cn;
            size_t oB = (size_t)rB * N + cn;
            float v0 = acc[i][j][0], v1 = acc[i][j][1];
            float v2 = acc[i][j][2], v3 = acc[i][j][3];
            if (ADD) {
                v0 += Cadd[oA]; v1 += Cadd[oA + 1];
                v2 += Cadd[oB]; v3 += Cadd[oB + 1];
            }
            if (MASK) {
                v0 = (Ht[oA] > 0)     ? v0 * scale : NEG_BIG;
                v1 = (Ht[oA + 1] > 0) ? v1 * scale : NEG_BIG;
                v2 = (Ht[oB] > 0)     ? v2 * scale : NEG_BIG;
                v3 = (Ht[oB + 1] > 0) ? v3 * scale : NEG_BIG;
            }
            C[oA] = v0; C[oA + 1] = v1;
            C[oB] = v2; C[oB + 1] = v3;
        }
    }
}

// ---------------------------------------------------------------------------
// Launch
// ---------------------------------------------------------------------------
template <int MODE, bool ADD, bool MASK>
static inline int smem_bytes_for() {
    constexpr int ASZ = (MODE == 2) ? BK * KM_LD : BM * RM_LD;
    constexpr int BSZ = (MODE == 1) ? BN * RM_LD : BK * KM_LD;
    return 2 * (ASZ + BSZ) * (int)sizeof(float);
}

extern "C" void kernel_launch(void* const* d_in, const int* in_sizes, int n_in,
                              void* d_out, int out_size) {
    const float* hidden   = (const float*)d_in[0];   // [B,N,D]
    const int*   ht       = (const int*)d_in[1];     // [B,E,N]
    const float* edge_emb = (const float*)d_in[2];   // [B,E,D]
    const float* wnk      = (const float*)d_in[3];   // [D,D]
    const float* wek      = (const float*)d_in[4];   // [D,D]
    const float* gam      = (const float*)d_in[5];   // [D]
    const float* bet      = (const float*)d_in[6];   // [D]
    float* out = (float*)d_out;                      // [B,N,D]

    float *eln, *nk, *eh, *ek, *sc;
    cudaGetSymbolAddress((void**)&eln, g_edge_ln);
    cudaGetSymbolAddress((void**)&nk, g_node_k);
    cudaGetSymbolAddress((void**)&eh, g_edge_h);
    cudaGetSymbolAddress((void**)&ek, g_edge_k);
    cudaGetSymbolAddress((void**)&sc, g_scores);

    const size_t sED = (size_t)EE * DD;
    const size_t sND = (size_t)NN * DD;
    const size_t sEN = (size_t)EE * NN;

    // opt-in to >48KB dynamic smem (idempotent; host-side, capture-safe)
    static bool attr_done = false;
    if (!attr_done) {
        cudaFuncSetAttribute(mma_gemm<0, false, false>,
                             cudaFuncAttributeMaxDynamicSharedMemorySize,
                             smem_bytes_for<0, false, false>());
        cudaFuncSetAttribute(mma_gemm<0, true, false>,
                             cudaFuncAttributeMaxDynamicSharedMemorySize,
                             smem_bytes_for<0, true, false>());
        cudaFuncSetAttribute(mma_gemm<1, false, true>,
                             cudaFuncAttributeMaxDynamicSharedMemorySize,
                             smem_bytes_for<1, false, true>());
        cudaFuncSetAttribute(mma_gemm<2, false, false>,
                             cudaFuncAttributeMaxDynamicSharedMemorySize,
                             smem_bytes_for<2, false, false>());
        attr_done = true;
    }

    const int smem_nn  = smem_bytes_for<0, false, false>();
    const int smem_add = smem_bytes_for<0, true, false>();
    const int smem_abt = smem_bytes_for<1, false, true>();
    const int smem_tn  = smem_bytes_for<2, false, false>();

    // 1. edge_ln = layernorm(edge_emb)
    ln_kernel<<<BB * EE, 256>>>(edge_emb, gam, bet, eln);

    // 2. node_k = hidden @ wnk   (flatten batch: M=B*N, N=D, K=D)
    mma_gemm<0, false, false><<<dim3(DD / BN, (BB * NN) / BM, 1), 256, smem_nn>>>(
        hidden, wnk, nullptr, nullptr, nk,
        BB * NN, DD, DD, DD, 1.f, 0, 0, 0, 0);

    // 3. scores[b,e,n] = mask(ht, scale * edge_ln . node_k^T)   (M=E, N=N, K=D)
    mma_gemm<1, false, true><<<dim3(NN / BN, EE / BM, BB), 256, smem_abt>>>(
        eln, nk, nullptr, ht, sc,
        EE, NN, DD, DD, SCALE_F, sED, sND, sEN, sEN);

    // 4. softmax over n
    softmax_kernel<<<BB * EE, 256>>>(sc, NN);

    // 5. edge_h = attn @ hidden + edge_ln   (M=E, N=D, K=N)
    mma_gemm<0, true, false><<<dim3(DD / BN, EE / BM, BB), 256, smem_add>>>(
        sc, hidden, eln, nullptr, eh,
        EE, DD, NN, NN, 1.f, sEN, sND, sED, sED);

    // 6. edge_k = edge_h @ wek   (flatten batch: M=B*E, N=D, K=D)
    mma_gemm<0, false, false><<<dim3(DD / BN, (BB * EE) / BM, 1), 256, smem_nn>>>(
        eh, wek, nullptr, nullptr, ek,
        BB * EE, DD, DD, DD, 1.f, 0, 0, 0, 0);

    // 7. scores[b,e,n] = mask(ht, scale * edge_k . node_k^T)
    mma_gemm<1, false, true><<<dim3(NN / BN, EE / BM, BB), 256, smem_abt>>>(
        ek, nk, nullptr, ht, sc,
        EE, NN, DD, DD, SCALE_F, sED, sND, sEN, sEN);

    // 8. softmax over n (== softmax over axis=1 of [B,N,E])
    softmax_kernel<<<BB * EE, 256>>>(sc, NN);

    // 9. out[n,d] = sum_e attn2[e,n] * edge_h[e,d]   (A^T B: M=N, N=D, K=E, lda=NN)
    mma_gemm<2, false, false><<<dim3(DD / BN, NN / BM, BB), 256, smem_tn>>>(
        sc, eh, nullptr, nullptr, out,
        NN, DD, EE, NN, 1.f, sEN, sED, sND, 0);
}

// round 12
// speedup vs baseline: 4.3908x; 1.0076x over previous
#include <cuda_runtime.h>
#include <cuda_bf16.h>
#include <cstdint>
#include <cstddef>

// Problem shapes
#define BB 8
#define NN 4096
#define EE 2048
#define DD 256
#define SCALE_F (0.0625f)            // 1/sqrt(256)
#define NEG_BIG (-9000000000000000.0f)
#define LN_EPS_F (1e-5f)

// GEMM tiling
#define BM 128
#define BN 128
#define BK 32
#define NSTAGE 3
#define RM_LD 36     // row-major (K-contig) smem row stride (16B aligned, conflict-free)
#define KM_LD 136    // k-major (N-contig) smem row stride (16B aligned, conflict-free)

// ---------------------------------------------------------------------------
// Scratch (device globals: no allocation allowed)
// ---------------------------------------------------------------------------
__device__ float g_edge_ln[(size_t)BB * EE * DD];   // 16 MiB
__device__ float g_node_k[(size_t)BB * NN * DD];    // 32 MiB
__device__ float g_edge_h[(size_t)BB * EE * DD];    // 16 MiB
__device__ float g_edge_k[(size_t)BB * EE * DD];    // 16 MiB
__device__ float g_scores[(size_t)BB * EE * NN];    // 256 MiB (reused stage1+2)

// ---------------------------------------------------------------------------
// Helpers
// ---------------------------------------------------------------------------
__device__ __forceinline__ float warpMax(float v) {
#pragma unroll
    for (int o = 16; o > 0; o >>= 1)
        v = fmaxf(v, __shfl_xor_sync(0xffffffffu, v, o));
    return v;
}
__device__ __forceinline__ float warpSum(float v) {
#pragma unroll
    for (int o = 16; o > 0; o >>= 1)
        v += __shfl_xor_sync(0xffffffffu, v, o);
    return v;
}

// fp32 -> tf32 bits with round-to-nearest (applied in fragment path)
__device__ __forceinline__ uint32_t tf_bits(float x) {
    uint32_t u;
    asm("cvt.rna.tf32.f32 %0, %1;" : "=r"(u) : "f"(x));
    return u;
}

__device__ __forceinline__ void mma_tf32(float c[4],
                                         uint32_t a0, uint32_t a1, uint32_t a2, uint32_t a3,
                                         uint32_t b0, uint32_t b1) {
    asm volatile(
        "mma.sync.aligned.m16n8k8.row.col.f32.tf32.tf32.f32 "
        "{%0,%1,%2,%3}, {%4,%5,%6,%7}, {%8,%9}, {%0,%1,%2,%3};"
        : "+f"(c[0]), "+f"(c[1]), "+f"(c[2]), "+f"(c[3])
        : "r"(a0), "r"(a1), "r"(a2), "r"(a3), "r"(b0), "r"(b1));
}

// 16B global->shared async copy
__device__ __forceinline__ void cpa16(float* dst_smem, const float* src_gmem) {
    uint32_t d = (uint32_t)__cvta_generic_to_shared(dst_smem);
    asm volatile("cp.async.cg.shared.global [%0], [%1], 16;\n" :: "r"(d), "l"(src_gmem));
}
#define CP_COMMIT() asm volatile("cp.async.commit_group;\n" ::: "memory")
#define CP_WAIT1()  asm volatile("cp.async.wait_group 1;\n" ::: "memory")

// ---------------------------------------------------------------------------
// LayerNorm: one block (256 thr) per row of D=256
// ---------------------------------------------------------------------------
__global__ void ln_kernel(const float* __restrict__ x,
                          const float* __restrict__ gam,
                          const float* __restrict__ bet,
                          float* __restrict__ y) {
    size_t row = blockIdx.x;
    int t = threadIdx.x;
    int w = t >> 5, l = t & 31;
    __shared__ float sred[8];

    float v = x[row * DD + t];

    float s = warpSum(v);
    if (l == 0) sred[w] = s;
    __syncthreads();
    if (t < 32) {
        float x2 = (l < 8) ? sred[l] : 0.f;
        x2 = warpSum(x2);
        if (l == 0) sred[0] = x2;
    }
    __syncthreads();
    float mu = sred[0] * (1.0f / DD);
    __syncthreads();

    float d = v - mu;
    float q = warpSum(d * d);
    if (l == 0) sred[w] = q;
    __syncthreads();
    if (t < 32) {
        float x2 = (l < 8) ? sred[l] : 0.f;
        x2 = warpSum(x2);
        if (l == 0) sred[0] = x2;
    }
    __syncthreads();
    float var = sred[0] * (1.0f / DD);

    y[row * DD + t] = gam[t] * d * rsqrtf(var + LN_EPS_F) + bet[t];
}

// ---------------------------------------------------------------------------
// Row softmax over L=4096: one block (256 thr) per row (already at DRAM roofline)
// ---------------------------------------------------------------------------
__global__ void softmax_kernel(float* __restrict__ S, int L) {
    float* row = S + (size_t)blockIdx.x * L;
    int t = threadIdx.x;
    int w = t >> 5, l = t & 31;
    const int PER = 16;
    __shared__ float sred[8];

    float v[PER];
    float mx = -3.4e38f;
#pragma unroll
    for (int i = 0; i < PER; i++) {
        v[i] = row[t + i * 256];
        mx = fmaxf(mx, v[i]);
    }
    mx = warpMax(mx);
    if (l == 0) sred[w] = mx;
    __syncthreads();
    if (t < 32) {
        float x2 = (l < 8) ? sred[l] : -3.4e38f;
        x2 = warpMax(x2);
        if (l == 0) sred[0] = x2;
    }
    __syncthreads();
    mx = sred[0];
    __syncthreads();

    float s = 0.f;
#pragma unroll
    for (int i = 0; i < PER; i++) {
        v[i] = __expf(v[i] - mx);
        s += v[i];
    }
    s = warpSum(s);
    if (l == 0) sred[w] = s;
    __syncthreads();
    if (t < 32) {
        float x2 = (l < 8) ? sred[l] : 0.f;
        x2 = warpSum(x2);
        if (l == 0) sred[0] = x2;
    }
    __syncthreads();
    float inv = 1.0f / sred[0];
#pragma unroll
    for (int i = 0; i < PER; i++)
        row[t + i * 256] = v[i] * inv;
}

// ---------------------------------------------------------------------------
// Unified tf32 tensor-core GEMM, 3-stage cp.async pipeline (1 barrier/tile).
//   MODE 0 (nn):  C = A[M,K] * B[K,N]            lda=K, ldb=N
//   MODE 1 (abt): C = A[M,K] * B[N,K]^T          lda=K, ldb=K
//   MODE 2 (tn):  C = A[K,M]^T * B[K,N]          lda passed, ldb=N
// ADD: += Cadd ; MASK: C = Ht>0 ? v*scale : NEG_BIG
// Block: 256 thr = 8 warps (4x2), block tile 128x128, warp tile 32x64.
// All dims are multiples of the tile for this problem; K/BK >= 2 always.
// ---------------------------------------------------------------------------
template <int MODE, bool ADD, bool MASK>
__global__ __launch_bounds__(256, 2)
void mma_gemm(const float* __restrict__ A, const float* __restrict__ B,
              const float* __restrict__ Cadd, const int* __restrict__ Ht,
              float* __restrict__ C,
              int M, int N, int K, int lda, float scale,
              size_t sA, size_t sB, size_t sC, size_t sAux) {
    int bz = blockIdx.z;
    A += (size_t)bz * sA;
    B += (size_t)bz * sB;
    C += (size_t)bz * sC;
    if (ADD) Cadd += (size_t)bz * sAux;
    if (MASK) Ht += (size_t)bz * sAux;

    constexpr int ASZ = (MODE == 2) ? BK * KM_LD : BM * RM_LD;
    constexpr int BSZ = (MODE == 1) ? BN * RM_LD : BK * KM_LD;
    constexpr int STAGE = ASZ + BSZ;
    extern __shared__ float smem[];

    const int t = threadIdx.x;
    const int lane = t & 31, wid = t >> 5;
    const int wm = wid >> 1, wn = wid & 1;
    const int grp = lane >> 2, thr = lane & 3;
    const int row0 = blockIdx.y * BM, col0 = blockIdx.x * BN;
    const int ldb = (MODE == 1) ? K : N;

    // ---- async tile loader into stage s ----
    auto load_tile = [&](int s, int k0) {
        float* As = smem + s * STAGE;
        float* Bs = As + ASZ;
        if (MODE != 2) {
            // A [M,K] K-contig -> As[m][k]
#pragma unroll
            for (int i = 0; i < 4; i++) {
                int r = (t >> 3) + i * 32;
                int k4 = (t & 7) * 4;
                cpa16(&As[r * RM_LD + k4], &A[(size_t)(row0 + r) * lda + k0 + k4]);
            }
        } else {
            // A [K,M] M-contig -> As[k][m]
#pragma unroll
            for (int i = 0; i < 4; i++) {
                int kk = (t >> 5) + i * 8;
                int c4 = (t & 31) * 4;
                cpa16(&As[kk * KM_LD + c4], &A[(size_t)(k0 + kk) * lda + row0 + c4]);
            }
        }
        if (MODE != 1) {
            // B [K,N] N-contig -> Bs[k][n]
#pragma unroll
            for (int i = 0; i < 4; i++) {
                int kk = (t >> 5) + i * 8;
                int c4 = (t & 31) * 4;
                cpa16(&Bs[kk * KM_LD + c4], &B[(size_t)(k0 + kk) * ldb + col0 + c4]);
            }
        } else {
            // B [N,K] K-contig -> Bs[n][k]
#pragma unroll
            for (int i = 0; i < 4; i++) {
                int r = (t >> 3) + i * 32;
                int k4 = (t & 7) * 4;
                cpa16(&Bs[r * RM_LD + k4], &B[(size_t)(col0 + r) * ldb + k0 + k4]);
            }
        }
    };

    // ---- fragment loaders from stage buffers ----
    auto load_afrag = [&](const float* As, int kk, uint32_t af[2][4]) {
#pragma unroll
        for (int i = 0; i < 2; i++) {
            int m0 = wm * 32 + i * 16;
            if (MODE != 2) {
                af[i][0] = tf_bits(As[(m0 + grp) * RM_LD + kk + thr]);
                af[i][1] = tf_bits(As[(m0 + grp + 8) * RM_LD + kk + thr]);
                af[i][2] = tf_bits(As[(m0 + grp) * RM_LD + kk + thr + 4]);
                af[i][3] = tf_bits(As[(m0 + grp + 8) * RM_LD + kk + thr + 4]);
            } else {
                af[i][0] = tf_bits(As[(kk + thr) * KM_LD + m0 + grp]);
                af[i][1] = tf_bits(As[(kk + thr) * KM_LD + m0 + grp + 8]);
                af[i][2] = tf_bits(As[(kk + thr + 4) * KM_LD + m0 + grp]);
                af[i][3] = tf_bits(As[(kk + thr + 4) * KM_LD + m0 + grp + 8]);
            }
        }
    };
    auto load_bfrag = [&](const float* Bs, int kk, int j, uint32_t& b0, uint32_t& b1) {
        int n0 = wn * 64 + j * 8;
        if (MODE != 1) {
            b0 = tf_bits(Bs[(kk + thr) * KM_LD + n0 + grp]);
            b1 = tf_bits(Bs[(kk + thr + 4) * KM_LD + n0 + grp]);
        } else {
            b0 = tf_bits(Bs[(n0 + grp) * RM_LD + kk + thr]);
            b1 = tf_bits(Bs[(n0 + grp) * RM_LD + kk + thr + 4]);
        }
    };

    float acc[2][8][4];
#pragma unroll
    for (int i = 0; i < 2; i++)
#pragma unroll
        for (int j = 0; j < 8; j++)
#pragma unroll
            for (int q = 0; q < 4; q++) acc[i][j][q] = 0.f;

    const int ntiles = K / BK;

    // prologue: 2 stages in flight (ntiles >= 8 for all call sites)
    load_tile(0, 0);
    CP_COMMIT();
    load_tile(1, BK);
    CP_COMMIT();

    int stage = 0;
    for (int kt = 0; kt < ntiles; kt++) {
        CP_WAIT1();              // tile kt landed (<=1 younger group pending)
        __syncthreads();         // also: everyone done reading buffer (kt-1)%3

        // refill buffer (kt+2)%3 == buffer of tile kt-1 (safe after the barrier)
        if (kt + 2 < ntiles)
            load_tile((stage + 2 >= NSTAGE) ? stage + 2 - NSTAGE : stage + 2,
                      (kt + 2) * BK);
        CP_COMMIT();             // empty group when nothing loaded: keeps count invariant

        const float* As = smem + stage * STAGE;
        const float* Bs = As + ASZ;

        // ---- compute: 4 k8 steps, A-frag double buffer + B-frag rotation ----
        uint32_t af[2][4], afn[2][4];
        load_afrag(As, 0, af);
#pragma unroll
        for (int kk = 0; kk < BK; kk += 8) {
            if (kk + 8 < BK) load_afrag(As, kk + 8, afn);
            uint32_t b0c, b1c, b0n, b1n;
            load_bfrag(Bs, kk, 0, b0c, b1c);
#pragma unroll
            for (int j = 0; j < 8; j++) {
                if (j < 7) load_bfrag(Bs, kk, j + 1, b0n, b1n);
#pragma unroll
                for (int i = 0; i < 2; i++)
                    mma_tf32(acc[i][j], af[i][0], af[i][1], af[i][2], af[i][3], b0c, b1c);
                b0c = b0n; b1c = b1n;
            }
#pragma unroll
            for (int i = 0; i < 2; i++)
#pragma unroll
                for (int q = 0; q < 4; q++) af[i][q] = afn[i][q];
        }

        stage = (stage + 1 >= NSTAGE) ? 0 : stage + 1;
    }

    // ---- epilogue (vectorized float2/int2) ----
#pragma unroll
    for (int i = 0; i < 2; i++) {
        int rA = row0 + wm * 32 + i * 16 + grp;
        int rB = rA + 8;
#pragma unroll
        for (int j = 0; j < 8; j++) {
            int cn = col0 + wn * 64 + j * 8 + thr * 2;
            size_t oA = (size_t)rA * N + cn;
            size_t oB = (size_t)rB * N + cn;
            float v0 = acc[i][j][0], v1 = acc[i][j][1];
            float v2 = acc[i][j][2], v3 = acc[i][j][3];
            if (ADD) {
                float2 cA = *(const float2*)&Cadd[oA];
                float2 cB = *(const float2*)&Cadd[oB];
                v0 += cA.x; v1 += cA.y;
                v2 += cB.x; v3 += cB.y;
            }
            if (MASK) {
                int2 hA = *(const int2*)&Ht[oA];
                int2 hB = *(const int2*)&Ht[oB];
                v0 = (hA.x > 0) ? v0 * scale : NEG_BIG;
                v1 = (hA.y > 0) ? v1 * scale : NEG_BIG;
                v2 = (hB.x > 0) ? v2 * scale : NEG_BIG;
                v3 = (hB.y > 0) ? v3 * scale : NEG_BIG;
            }
            *(float2*)&C[oA] = make_float2(v0, v1);
            *(float2*)&C[oB] = make_float2(v2, v3);
        }
    }
}

// ---------------------------------------------------------------------------
// Launch
// ---------------------------------------------------------------------------
template <int MODE, bool ADD, bool MASK>
static inline int smem_bytes_for() {
    constexpr int ASZ = (MODE == 2) ? BK * KM_LD : BM * RM_LD;
    constexpr int BSZ = (MODE == 1) ? BN * RM_LD : BK * KM_LD;
    return NSTAGE * (ASZ + BSZ) * (int)sizeof(float);
}

extern "C" void kernel_launch(void* const* d_in, const int* in_sizes, int n_in,
                              void* d_out, int out_size) {
    const float* hidden   = (const float*)d_in[0];   // [B,N,D]
    const int*   ht       = (const int*)d_in[1];     // [B,E,N]
    const float* edge_emb = (const float*)d_in[2];   // [B,E,D]
    const float* wnk      = (const float*)d_in[3];   // [D,D]
    const float* wek      = (const float*)d_in[4];   // [D,D]
    const float* gam      = (const float*)d_in[5];   // [D]
    const float* bet      = (const float*)d_in[6];   // [D]
    float* out = (float*)d_out;                      // [B,N,D]

    float *eln, *nk, *eh, *ek, *sc;
    cudaGetSymbolAddress((void**)&eln, g_edge_ln);
    cudaGetSymbolAddress((void**)&nk, g_node_k);
    cudaGetSymbolAddress((void**)&eh, g_edge_h);
    cudaGetSymbolAddress((void**)&ek, g_edge_k);
    cudaGetSymbolAddress((void**)&sc, g_scores);

    const size_t sED = (size_t)EE * DD;
    const size_t sND = (size_t)NN * DD;
    const size_t sEN = (size_t)EE * NN;

    // opt-in to >48KB dynamic smem (idempotent; host-side, capture-safe)
    static bool attr_done = false;
    if (!attr_done) {
        cudaFuncSetAttribute(mma_gemm<0, false, false>,
                             cudaFuncAttributeMaxDynamicSharedMemorySize,
                             smem_bytes_for<0, false, false>());
        cudaFuncSetAttribute(mma_gemm<0, true, false>,
                             cudaFuncAttributeMaxDynamicSharedMemorySize,
                             smem_bytes_for<0, true, false>());
        cudaFuncSetAttribute(mma_gemm<1, false, true>,
                             cudaFuncAttributeMaxDynamicSharedMemorySize,
                             smem_bytes_for<1, false, true>());
        cudaFuncSetAttribute(mma_gemm<2, false, false>,
                             cudaFuncAttributeMaxDynamicSharedMemorySize,
                             smem_bytes_for<2, false, false>());
        attr_done = true;
    }

    const int smem_nn  = smem_bytes_for<0, false, false>();
    const int smem_add = smem_bytes_for<0, true, false>();
    const int smem_abt = smem_bytes_for<1, false, true>();
    const int smem_tn  = smem_bytes_for<2, false, false>();

    // 1. edge_ln = layernorm(edge_emb)
    ln_kernel<<<BB * EE, 256>>>(edge_emb, gam, bet, eln);

    // 2. node_k = hidden @ wnk   (flatten batch: M=B*N, N=D, K=D)
    mma_gemm<0, false, false><<<dim3(DD / BN, (BB * NN) / BM, 1), 256, smem_nn>>>(
        hidden, wnk, nullptr, nullptr, nk,
        BB * NN, DD, DD, DD, 1.f, 0, 0, 0, 0);

    // 3. scores[b,e,n] = mask(ht, scale * edge_ln . node_k^T)   (M=E, N=N, K=D)
    mma_gemm<1, false, true><<<dim3(NN / BN, EE / BM, BB), 256, smem_abt>>>(
        eln, nk, nullptr, ht, sc,
        EE, NN, DD, DD, SCALE_F, sED, sND, sEN, sEN);

    // 4. softmax over n
    softmax_kernel<<<BB * EE, 256>>>(sc, NN);

    // 5. edge_h = attn @ hidden + edge_ln   (M=E, N=D, K=N)
    mma_gemm<0, true, false><<<dim3(DD / BN, EE / BM, BB), 256, smem_add>>>(
        sc, hidden, eln, nullptr, eh,
        EE, DD, NN, NN, 1.f, sEN, sND, sED, sED);

    // 6. edge_k = edge_h @ wek   (flatten batch: M=B*E, N=D, K=D)
    mma_gemm<0, false, false><<<dim3(DD / BN, (BB * EE) / BM, 1), 256, smem_nn>>>(
        eh, wek, nullptr, nullptr, ek,
        BB * EE, DD, DD, DD, 1.f, 0, 0, 0, 0);

    // 7. scores[b,e,n] = mask(ht, scale * edge_k . node_k^T)
    mma_gemm<1, false, true><<<dim3(NN / BN, EE / BM, BB), 256, smem_abt>>>(
        ek, nk, nullptr, ht, sc,
        EE, NN, DD, DD, SCALE_F, sED, sND, sEN, sEN);

    // 8. softmax over n (== softmax over axis=1 of [B,N,E])
    softmax_kernel<<<BB * EE, 256>>>(sc, NN);

    // 9. out[n,d] = sum_e attn2[e,n] * edge_h[e,d]   (A^T B: M=N, N=D, K=E, lda=NN)
    mma_gemm<2, false, false><<<dim3(DD / BN, NN / BM, BB), 256, smem_tn>>>(
        sc, eh, nullptr, nullptr, out,
        NN, DD, EE, NN, 1.f, sEN, sED, sND, 0);
}

// round 15
// speedup vs baseline: 6.7833x; 1.5449x over previous
#include <cuda_runtime.h>
#include <cuda_fp16.h>
#include <cstdint>
#include <cstddef>

// Problem shapes
#define BB 8
#define NN 4096
#define EE 2048
#define DD 256
#define SCALE_F (0.0625f)            // 1/sqrt(256)
#define NEG_BIG (-9000000000000000.0f)
#define LN_EPS_F (1e-5f)

// GEMM tiling (fp16 operands)
#define BM 128
#define BN 128
#define BK 32
#define NSTAGE 3
#define LD_H 40                       // halves per smem row (80 B: 16B-aligned, bank-conflict-free)
#define ASZ_H (BM * LD_H)             // halves per operand tile
#define STAGE_H (2 * ASZ_H)
#define SMEM_BYTES (NSTAGE * STAGE_H * 2)   // 61440 B

// ---------------------------------------------------------------------------
// Scratch (device globals: no allocation allowed)
// ---------------------------------------------------------------------------
__device__ float  g_eln   [(size_t)BB * EE * DD];   // fp32 (residual add)
__device__ __half g_eln_h [(size_t)BB * EE * DD];
__device__ __half g_hid_h [(size_t)BB * NN * DD];
__device__ __half g_hidT_h[(size_t)BB * DD * NN];
__device__ __half g_nk_h  [(size_t)BB * NN * DD];
__device__ __half g_eh_h  [(size_t)BB * EE * DD];
__device__ __half g_ehT_h [(size_t)BB * DD * EE];
__device__ __half g_ek_h  [(size_t)BB * EE * DD];
__device__ __half g_wnkT_h[DD * DD];
__device__ __half g_wekT_h[DD * DD];
__device__ float  g_sc    [(size_t)BB * EE * NN];   // fp32 masked scores (256 MiB)
__device__ __half g_sc_h  [(size_t)BB * EE * NN];   // fp16 attn (128 MiB)
__device__ __half g_scT_h [(size_t)BB * NN * EE];   // fp16 attn transposed (128 MiB)

// ---------------------------------------------------------------------------
// Helpers
// ---------------------------------------------------------------------------
__device__ __forceinline__ float warpMax(float v) {
#pragma unroll
    for (int o = 16; o > 0; o >>= 1)
        v = fmaxf(v, __shfl_xor_sync(0xffffffffu, v, o));
    return v;
}
__device__ __forceinline__ float warpSum(float v) {
#pragma unroll
    for (int o = 16; o > 0; o >>= 1)
        v += __shfl_xor_sync(0xffffffffu, v, o);
    return v;
}

__device__ __forceinline__ void mma_f16(float c[4], const uint32_t a[4],
                                        uint32_t b0, uint32_t b1) {
    asm volatile(
        "mma.sync.aligned.m16n8k16.row.col.f32.f16.f16.f32 "
        "{%0,%1,%2,%3}, {%4,%5,%6,%7}, {%8,%9}, {%0,%1,%2,%3};"
        : "+f"(c[0]), "+f"(c[1]), "+f"(c[2]), "+f"(c[3])
        : "r"(a[0]), "r"(a[1]), "r"(a[2]), "r"(a[3]), "r"(b0), "r"(b1));
}

// 16B global->shared async copy
__device__ __forceinline__ void cpa16(__half* dst_smem, const __half* src_gmem) {
    uint32_t d = (uint32_t)__cvta_generic_to_shared(dst_smem);
    asm volatile("cp.async.cg.shared.global [%0], [%1], 16;\n" :: "r"(d), "l"(src_gmem));
}
#define CP_COMMIT() asm volatile("cp.async.commit_group;\n" ::: "memory")
#define CP_WAIT1()  asm volatile("cp.async.wait_group 1;\n" ::: "memory")

// ---------------------------------------------------------------------------
// Elementwise fp32 -> fp16 convert (n multiple of 1024)
// ---------------------------------------------------------------------------
__global__ void cvt_kernel(const float* __restrict__ s, __half* __restrict__ d, size_t n) {
    size_t i = ((size_t)blockIdx.x * blockDim.x + threadIdx.x) * 4;
    if (i >= n) return;
    float4 v = *(const float4*)&s[i];
    *(__half2*)&d[i]     = __floats2half2_rn(v.x, v.y);
    *(__half2*)&d[i + 2] = __floats2half2_rn(v.z, v.w);
}

// ---------------------------------------------------------------------------
// Tiled transpose fp32 -> fp16: dst[c,r] = (half)src[r,c]. block (32,8)
// ---------------------------------------------------------------------------
__global__ void transpose_cvt_kernel(const float* __restrict__ src, __half* __restrict__ dst,
                                     int R, int C, size_t sS, size_t sD) {
    __shared__ float tile[32][33];
    const float* s = src + (size_t)blockIdx.z * sS;
    __half* d = dst + (size_t)blockIdx.z * sD;
    int x = blockIdx.x * 32 + threadIdx.x;
    int y = blockIdx.y * 32 + threadIdx.y;
#pragma unroll
    for (int i = 0; i < 32; i += 8)
        tile[threadIdx.y + i][threadIdx.x] = s[(size_t)(y + i) * C + x];
    __syncthreads();
    int x2 = blockIdx.y * 32 + threadIdx.x;
    int y2 = blockIdx.x * 32 + threadIdx.y;
#pragma unroll
    for (int i = 0; i < 32; i += 8)
        d[(size_t)(y2 + i) * R + x2] = __float2half_rn(tile[threadIdx.x][threadIdx.y + i]);
}

// ---------------------------------------------------------------------------
// Tiled transpose fp16 -> fp16
// ---------------------------------------------------------------------------
__global__ void transpose_h_kernel(const __half* __restrict__ src, __half* __restrict__ dst,
                                   int R, int C, size_t sS, size_t sD) {
    __shared__ __half tile[32][33];
    const __half* s = src + (size_t)blockIdx.z * sS;
    __half* d = dst + (size_t)blockIdx.z * sD;
    int x = blockIdx.x * 32 + threadIdx.x;
    int y = blockIdx.y * 32 + threadIdx.y;
#pragma unroll
    for (int i = 0; i < 32; i += 8)
        tile[threadIdx.y + i][threadIdx.x] = s[(size_t)(y + i) * C + x];
    __syncthreads();
    int x2 = blockIdx.y * 32 + threadIdx.x;
    int y2 = blockIdx.x * 32 + threadIdx.y;
#pragma unroll
    for (int i = 0; i < 32; i += 8)
        d[(size_t)(y2 + i) * R + x2] = tile[threadIdx.x][threadIdx.y + i];
}

// ---------------------------------------------------------------------------
// LayerNorm: one block (256 thr) per row of D=256; writes fp32 + fp16
// ---------------------------------------------------------------------------
__global__ void ln_kernel(const float* __restrict__ x,
                          const float* __restrict__ gam,
                          const float* __restrict__ bet,
                          float* __restrict__ y, __half* __restrict__ yh) {
    size_t row = blockIdx.x;
    int t = threadIdx.x;
    int w = t >> 5, l = t & 31;
    __shared__ float sred[8];

    float v = x[row * DD + t];

    float s = warpSum(v);
    if (l == 0) sred[w] = s;
    __syncthreads();
    if (t < 32) {
        float x2 = (l < 8) ? sred[l] : 0.f;
        x2 = warpSum(x2);
        if (l == 0) sred[0] = x2;
    }
    __syncthreads();
    float mu = sred[0] * (1.0f / DD);
    __syncthreads();

    float d = v - mu;
    float q = warpSum(d * d);
    if (l == 0) sred[w] = q;
    __syncthreads();
    if (t < 32) {
        float x2 = (l < 8) ? sred[l] : 0.f;
        x2 = warpSum(x2);
        if (l == 0) sred[0] = x2;
    }
    __syncthreads();
    float var = sred[0] * (1.0f / DD);

    float r = gam[t] * d * rsqrtf(var + LN_EPS_F) + bet[t];
    y[row * DD + t] = r;
    yh[row * DD + t] = __float2half_rn(r);
}

// ---------------------------------------------------------------------------
// Row softmax over L=4096: reads fp32 scores, writes fp16 attn
// ---------------------------------------------------------------------------
__global__ void softmax_kernel(const float* __restrict__ S, __half* __restrict__ O, int L) {
    const float* row = S + (size_t)blockIdx.x * L;
    __half* orow = O + (size_t)blockIdx.x * L;
    int t = threadIdx.x;
    int w = t >> 5, l = t & 31;
    const int PER = 16;
    __shared__ float sred[8];

    float v[PER];
    float mx = -3.4e38f;
#pragma unroll
    for (int i = 0; i < PER; i++) {
        v[i] = row[t + i * 256];
        mx = fmaxf(mx, v[i]);
    }
    mx = warpMax(mx);
    if (l == 0) sred[w] = mx;
    __syncthreads();
    if (t < 32) {
        float x2 = (l < 8) ? sred[l] : -3.4e38f;
        x2 = warpMax(x2);
        if (l == 0) sred[0] = x2;
    }
    __syncthreads();
    mx = sred[0];
    __syncthreads();

    float s = 0.f;
#pragma unroll
    for (int i = 0; i < PER; i++) {
        v[i] = __expf(v[i] - mx);
        s += v[i];
    }
    s = warpSum(s);
    if (l == 0) sred[w] = s;
    __syncthreads();
    if (t < 32) {
        float x2 = (l < 8) ? sred[l] : 0.f;
        x2 = warpSum(x2);
        if (l == 0) sred[0] = x2;
    }
    __syncthreads();
    float inv = 1.0f / sred[0];
#pragma unroll
    for (int i = 0; i < PER; i++)
        orow[t + i * 256] = __float2half_rn(v[i] * inv);
}

// ---------------------------------------------------------------------------
// fp16 tensor-core GEMM:  C[M,N] = A[M,K] * B[N,K]^T  (both K-contig fp16)
// ADD: += Cadd(fp32) ;  MASK: C = Ht>0 ? v*scale : NEG_BIG (fp32 out)
// OUTH: C is fp16, else fp32.
// 3-stage cp.async pipeline; 256 thr = 8 warps (4x2); warp tile 32x64.
// All dims are multiples of the tile; K/BK >= 3 at every call site.
// ---------------------------------------------------------------------------
template <bool ADD, bool MASK, bool OUTH>
__global__ __launch_bounds__(256, 2)
void hgemm(const __half* __restrict__ A, const __half* __restrict__ B,
           const float* __restrict__ Cadd, const int* __restrict__ Ht,
           void* __restrict__ Cv,
           int M, int N, int K, float scale,
           size_t sA, size_t sB, size_t sC, size_t sAux) {
    const int bz = blockIdx.z;
    A += (size_t)bz * sA;
    B += (size_t)bz * sB;
    const size_t coff = (size_t)bz * sC;
    if (ADD) Cadd += (size_t)bz * sAux;
    if (MASK) Ht += (size_t)bz * sAux;

    extern __shared__ __half smem_h[];

    const int t = threadIdx.x;
    const int lane = t & 31, wid = t >> 5;
    const int wm = wid >> 1, wn = wid & 1;
    const int grp = lane >> 2, thr = lane & 3;
    const int row0 = blockIdx.y * BM, col0 = blockIdx.x * BN;

    // tile loader: 128 rows x 32 halves (64B) per operand -> 4 chunks/row
    auto load_tile = [&](int s, int k0) {
        __half* As = smem_h + s * STAGE_H;
        __half* Bs = As + ASZ_H;
#pragma unroll
        for (int i = 0; i < 2; i++) {
            int slot = t + i * 256;
            int r = slot >> 2, ch = slot & 3;
            cpa16(As + r * LD_H + ch * 8, &A[(size_t)(row0 + r) * K + k0 + ch * 8]);
            cpa16(Bs + r * LD_H + ch * 8, &B[(size_t)(col0 + r) * K + k0 + ch * 8]);
        }
    };

    float acc[2][8][4];
#pragma unroll
    for (int i = 0; i < 2; i++)
#pragma unroll
        for (int j = 0; j < 8; j++)
#pragma unroll
            for (int q = 0; q < 4; q++) acc[i][j][q] = 0.f;

    const int ntiles = K / BK;

    load_tile(0, 0);
    CP_COMMIT();
    load_tile(1, BK);
    CP_COMMIT();

    int stage = 0;
    for (int kt = 0; kt < ntiles; kt++) {
        CP_WAIT1();              // tile kt landed
        __syncthreads();         // buffer (kt-1)%3 fully consumed

        if (kt + 2 < ntiles)
            load_tile((stage + 2 >= NSTAGE) ? stage + 2 - NSTAGE : stage + 2,
                      (kt + 2) * BK);
        CP_COMMIT();             // empty group keeps wait-count invariant

        const __half* As = smem_h + stage * STAGE_H;
        const __half* Bs = As + ASZ_H;

#pragma unroll
        for (int kk = 0; kk < BK; kk += 16) {
            uint32_t a[2][4];
#pragma unroll
            for (int i = 0; i < 2; i++) {
                const __half* ap = As + (wm * 32 + i * 16 + grp) * LD_H + kk + thr * 2;
                a[i][0] = *(const uint32_t*)ap;
                a[i][1] = *(const uint32_t*)(ap + 8 * LD_H);
                a[i][2] = *(const uint32_t*)(ap + 8);
                a[i][3] = *(const uint32_t*)(ap + 8 * LD_H + 8);
            }
#pragma unroll
            for (int j = 0; j < 8; j++) {
                const __half* bp = Bs + (wn * 64 + j * 8 + grp) * LD_H + kk + thr * 2;
                uint32_t b0 = *(const uint32_t*)bp;
                uint32_t b1 = *(const uint32_t*)(bp + 8);
                mma_f16(acc[0][j], a[0], b0, b1);
                mma_f16(acc[1][j], a[1], b0, b1);
            }
        }

        stage = (stage + 1 >= NSTAGE) ? 0 : stage + 1;
    }

    // ---- epilogue ----
#pragma unroll
    for (int i = 0; i < 2; i++) {
        int rA = row0 + wm * 32 + i * 16 + grp;
        int rB = rA + 8;
#pragma unroll
        for (int j = 0; j < 8; j++) {
            int cn = col0 + wn * 64 + j * 8 + thr * 2;
            size_t oA = (size_t)rA * N + cn;
            size_t oB = (size_t)rB * N + cn;
            float v0 = acc[i][j][0], v1 = acc[i][j][1];
            float v2 = acc[i][j][2], v3 = acc[i][j][3];
            if (ADD) {
                float2 cA = *(const float2*)&Cadd[oA];
                float2 cB = *(const float2*)&Cadd[oB];
                v0 += cA.x; v1 += cA.y;
                v2 += cB.x; v3 += cB.y;
            }
            if (MASK) {
                int2 hA = *(const int2*)&Ht[oA];
                int2 hB = *(const int2*)&Ht[oB];
                v0 = (hA.x > 0) ? v0 * scale : NEG_BIG;
                v1 = (hA.y > 0) ? v1 * scale : NEG_BIG;
                v2 = (hB.x > 0) ? v2 * scale : NEG_BIG;
                v3 = (hB.y > 0) ? v3 * scale : NEG_BIG;
            }
            if (OUTH) {
                __half* C = (__half*)Cv;
                *(__half2*)&C[coff + oA] = __floats2half2_rn(v0, v1);
                *(__half2*)&C[coff + oB] = __floats2half2_rn(v2, v3);
            } else {
                float* C = (float*)Cv;
                *(float2*)&C[coff + oA] = make_float2(v0, v1);
                *(float2*)&C[coff + oB] = make_float2(v2, v3);
            }
        }
    }
}

// ---------------------------------------------------------------------------
// Launch
// ---------------------------------------------------------------------------
extern "C" void kernel_launch(void* const* d_in, const int* in_sizes, int n_in,
                              void* d_out, int out_size) {
    const float* hidden   = (const float*)d_in[0];   // [B,N,D]
    const int*   ht       = (const int*)d_in[1];     // [B,E,N]
    const float* edge_emb = (const float*)d_in[2];   // [B,E,D]
    const float* wnk      = (const float*)d_in[3];   // [D,D]
    const float* wek      = (const float*)d_in[4];   // [D,D]
    const float* gam      = (const float*)d_in[5];   // [D]
    const float* bet      = (const float*)d_in[6];   // [D]
    float* out = (float*)d_out;                      // [B,N,D]

    float *eln, *sc;
    __half *eln_h, *hid_h, *hidT_h, *nk_h, *eh_h, *ehT_h, *ek_h, *wnkT_h, *wekT_h, *sc_h, *scT_h;
    cudaGetSymbolAddress((void**)&eln,    g_eln);
    cudaGetSymbolAddress((void**)&eln_h,  g_eln_h);
    cudaGetSymbolAddress((void**)&hid_h,  g_hid_h);
    cudaGetSymbolAddress((void**)&hidT_h, g_hidT_h);
    cudaGetSymbolAddress((void**)&nk_h,   g_nk_h);
    cudaGetSymbolAddress((void**)&eh_h,   g_eh_h);
    cudaGetSymbolAddress((void**)&ehT_h,  g_ehT_h);
    cudaGetSymbolAddress((void**)&ek_h,   g_ek_h);
    cudaGetSymbolAddress((void**)&wnkT_h, g_wnkT_h);
    cudaGetSymbolAddress((void**)&wekT_h, g_wekT_h);
    cudaGetSymbolAddress((void**)&sc,     g_sc);
    cudaGetSymbolAddress((void**)&sc_h,   g_sc_h);
    cudaGetSymbolAddress((void**)&scT_h,  g_scT_h);

    const size_t sED = (size_t)EE * DD;
    const size_t sND = (size_t)NN * DD;
    const size_t sEN = (size_t)EE * NN;
    const size_t sDN = (size_t)DD * NN;
    const size_t sDE = (size_t)DD * EE;

    static bool attr_done = false;
    if (!attr_done) {
        cudaFuncSetAttribute(hgemm<false, false, true>,
                             cudaFuncAttributeMaxDynamicSharedMemorySize, SMEM_BYTES);
        cudaFuncSetAttribute(hgemm<false, true, false>,
                             cudaFuncAttributeMaxDynamicSharedMemorySize, SMEM_BYTES);
        cudaFuncSetAttribute(hgemm<true, false, true>,
                             cudaFuncAttributeMaxDynamicSharedMemorySize, SMEM_BYTES);
        cudaFuncSetAttribute(hgemm<false, false, false>,
                             cudaFuncAttributeMaxDynamicSharedMemorySize, SMEM_BYTES);
        attr_done = true;
    }

    dim3 tb(32, 8);

    // 0. conversions / transposes of inputs
    cvt_kernel<<<(BB * (size_t)NN * DD) / 4 / 256, 256>>>(hidden, hid_h, (size_t)BB * NN * DD);
    transpose_cvt_kernel<<<dim3(8, 8, 1), tb>>>(wnk, wnkT_h, DD, DD, 0, 0);
    transpose_cvt_kernel<<<dim3(8, 8, 1), tb>>>(wek, wekT_h, DD, DD, 0, 0);
    transpose_cvt_kernel<<<dim3(8, 128, 8), tb>>>(hidden, hidT_h, NN, DD, sND, sDN);

    // 1. edge_ln = layernorm(edge_emb)  (fp32 + fp16)
    ln_kernel<<<BB * EE, 256>>>(edge_emb, gam, bet, eln, eln_h);

    // 2. nk_h = hidden @ wnk   == hid_h[BN,256] . wnkT_h[256,256]^T   (fp16 out)
    hgemm<false, false, true><<<dim3(DD / BN, (BB * NN) / BM, 1), 256, SMEM_BYTES>>>(
        hid_h, wnkT_h, nullptr, nullptr, nk_h,
        BB * NN, DD, DD, 1.f, 0, 0, 0, 0);

    // 3. sc = mask(ht, scale * eln_h . nk_h^T)   (fp32 out)
    hgemm<false, true, false><<<dim3(NN / BN, EE / BM, BB), 256, SMEM_BYTES>>>(
        eln_h, nk_h, nullptr, ht, sc,
        EE, NN, DD, SCALE_F, sED, sND, sEN, sEN);

    // 4. softmax over n -> fp16 attn
    softmax_kernel<<<BB * EE, 256>>>(sc, sc_h, NN);

    // 5. eh_h = attn @ hidden + eln   == sc_h[E,4096] . hidT_h[256,4096]^T + eln
    hgemm<true, false, true><<<dim3(DD / BN, EE / BM, BB), 256, SMEM_BYTES>>>(
        sc_h, hidT_h, eln, nullptr, eh_h,
        EE, DD, NN, 1.f, sEN, sDN, sED, sED);

    // 6. ek_h = edge_h @ wek   == eh_h[BE,256] . wekT_h[256,256]^T
    hgemm<false, false, true><<<dim3(DD / BN, (BB * EE) / BM, 1), 256, SMEM_BYTES>>>(
        eh_h, wekT_h, nullptr, nullptr, ek_h,
        BB * EE, DD, DD, 1.f, 0, 0, 0, 0);

    // 7. sc = mask(ht, scale * ek_h . nk_h^T)
    hgemm<false, true, false><<<dim3(NN / BN, EE / BM, BB), 256, SMEM_BYTES>>>(
        ek_h, nk_h, nullptr, ht, sc,
        EE, NN, DD, SCALE_F, sED, sND, sEN, sEN);

    // 8. softmax over n -> fp16 attn2
    softmax_kernel<<<BB * EE, 256>>>(sc, sc_h, NN);

    // 9a. transposes for the gather GEMM: scT_h[N,E], ehT_h[D,E]
    transpose_h_kernel<<<dim3(128, 64, 8), tb>>>(sc_h, scT_h, EE, NN, sEN, sEN);
    transpose_h_kernel<<<dim3(8, 64, 8), tb>>>(eh_h, ehT_h, EE, DD, sED, sDE);

    // 9b. out[n,d] = attn2^T . edge_h == scT_h[N,2048] . ehT_h[256,2048]^T  (fp32 out)
    hgemm<false, false, false><<<dim3(DD / BN, NN / BM, BB), 256, SMEM_BYTES>>>(
        scT_h, ehT_h, nullptr, nullptr, out,
        NN, DD, EE, 1.f, sEN, sDE, sND, 0);
}